// round 1
// baseline (speedup 1.0000x reference)
#include <cuda_runtime.h>

#define HW   3136
#define WID  56
#define NHD  8
#define CHN  8
#define SCALE 0.17677669529663687f  // (256/8)^-0.5

// Scratch (alloc-free rule: __device__ globals)
__device__ float g_qkv[16 * 192 * HW];   // (B, 192, H*W)
__device__ float g_hid[16 * 64  * HW];   // (B, 64, H*W)

// ---------------------------------------------------------------------------
// Tiled fp32 GEMM:  C[b, m, n] = sum_k A[m,k] * X[b, k, n] + bias[m]
// BM=BN=64, BK=16, 256 threads, 4x4 per-thread tile. M,N,K all divide tiles.
// ---------------------------------------------------------------------------
__global__ void gemm_bias(const float* __restrict__ A, const float* __restrict__ X,
                          const float* __restrict__ bias, float* __restrict__ C,
                          int M, int N, int K, long xbs, long cbs)
{
    __shared__ float sA[16][64];
    __shared__ float sB[16][64];
    const int tid = threadIdx.x;
    const int m0 = blockIdx.y * 64;
    const int n0 = blockIdx.x * 64;
    const float* Xb = X + (long)blockIdx.z * xbs;
    float*       Cb = C + (long)blockIdx.z * cbs;

    const int aRow = tid >> 2;           // 0..63 (m within tile)
    const int aCol = (tid & 3) * 4;      // 0..12 (k within tile)
    const int bRow = tid >> 4;           // 0..15 (k)
    const int bCol = (tid & 15) * 4;     // 0..60 (n)
    const int ty   = tid >> 4;           // 0..15
    const int tx   = tid & 15;           // 0..15

    float acc[4][4];
    #pragma unroll
    for (int i = 0; i < 4; i++)
        #pragma unroll
        for (int j = 0; j < 4; j++) acc[i][j] = 0.f;

    for (int k0 = 0; k0 < K; k0 += 16) {
        float4 av = *(const float4*)&A[(long)(m0 + aRow) * K + k0 + aCol];
        sA[aCol + 0][aRow] = av.x;
        sA[aCol + 1][aRow] = av.y;
        sA[aCol + 2][aRow] = av.z;
        sA[aCol + 3][aRow] = av.w;
        *(float4*)&sB[bRow][bCol] =
            *(const float4*)&Xb[(long)(k0 + bRow) * N + n0 + bCol];
        __syncthreads();
        #pragma unroll
        for (int k = 0; k < 16; k++) {
            float4 a = *(const float4*)&sA[k][ty * 4];
            float4 b = *(const float4*)&sB[k][tx * 4];
            float ar[4] = {a.x, a.y, a.z, a.w};
            float br[4] = {b.x, b.y, b.z, b.w};
            #pragma unroll
            for (int i = 0; i < 4; i++)
                #pragma unroll
                for (int j = 0; j < 4; j++)
                    acc[i][j] = fmaf(ar[i], br[j], acc[i][j]);
        }
        __syncthreads();
    }
    #pragma unroll
    for (int i = 0; i < 4; i++) {
        const int m = m0 + ty * 4 + i;
        const float bs = bias[m];
        #pragma unroll
        for (int j = 0; j < 4; j++)
            Cb[(long)m * N + n0 + tx * 4 + j] = acc[i][j] + bs;
    }
}

// ---------------------------------------------------------------------------
// Fused sliding attention. One block = 14x14 pixel tile for one (batch, head).
// k/v halo (16x16 x 8ch each) in smem; unfold + depthwise-conv + biases + rpb,
// 9-tap softmax, weighted V sum -> g_hid.
// ---------------------------------------------------------------------------
__global__ void attn_kernel(const float* __restrict__ qkv,
                            const float* __restrict__ dc_b,
                            const float* __restrict__ dc1_w,
                            const float* __restrict__ dc1_b,
                            const float* __restrict__ rpb,
                            float* __restrict__ hid)
{
    __shared__ float sk[CHN][16][16];
    __shared__ float sv[CHN][16][16];
    __shared__ float swt[648];   // dc1_w: (c*9+a)*9 + t
    __shared__ float scb[72];    // dc_b + dc1_b
    __shared__ float srp[9];     // rpb for this head

    const int tid = threadIdx.x;
    const int h = blockIdx.y;
    const int b = blockIdx.z;
    const int tileY = blockIdx.x >> 2, tileX = blockIdx.x & 3;
    const int gy0 = tileY * 14 - 1, gx0 = tileX * 14 - 1;

    for (int i = tid; i < 648; i += 256) swt[i] = dc1_w[i];
    if (tid < 72) scb[tid] = dc_b[tid] + dc1_b[tid];
    if (tid < 9)  srp[tid] = rpb[h * 9 + tid];

    {   // halo load (all 256 threads, one (r,s) each, 8 channels k + v)
        const int r = tid >> 4, s = tid & 15;
        const int gy = gy0 + r, gx = gx0 + s;
        const bool ok = (gy >= 0) & (gy < WID) & (gx >= 0) & (gx < WID);
        const int off = ok ? gy * WID + gx : 0;
        const float* kb = qkv + ((long)(b * 192 + h * 24 + 8)) * HW + off;
        #pragma unroll
        for (int c = 0; c < CHN; c++) {
            sk[c][r][s] = ok ? kb[c * HW]        : 0.f;
            sv[c][r][s] = ok ? kb[(8 + c) * HW]  : 0.f;
        }
    }
    __syncthreads();

    if (tid >= 196) return;
    const int ly = tid / 14, lx = tid - ly * 14;
    const int gy = tileY * 14 + ly, gx = tileX * 14 + lx;
    const int pix = gy * WID + gx;

    float q[CHN];
    {
        const float* qp = qkv + ((long)(b * 192 + h * 24)) * HW + pix;
        #pragma unroll
        for (int c = 0; c < CHN; c++) q[c] = qp[c * HW] * SCALE;
    }

    float logit[9];
    #pragma unroll
    for (int a = 0; a < 9; a++) logit[a] = 0.f;

    #pragma unroll 1
    for (int c = 0; c < CHN; c++) {
        float nb[9];
        #pragma unroll
        for (int t = 0; t < 9; t++) nb[t] = sk[c][ly + t / 3][lx + t % 3];
        #pragma unroll
        for (int a = 0; a < 9; a++) {
            float kv = nb[a] + scb[c * 9 + a] + srp[a];
            #pragma unroll
            for (int t = 0; t < 9; t++)
                kv = fmaf(swt[(c * 9 + a) * 9 + t], nb[t], kv);
            logit[a] = fmaf(q[c], kv, logit[a]);
        }
    }

    // softmax over the 9 taps
    float mx = logit[0];
    #pragma unroll
    for (int a = 1; a < 9; a++) mx = fmaxf(mx, logit[a]);
    float s = 0.f;
    #pragma unroll
    for (int a = 0; a < 9; a++) { logit[a] = __expf(logit[a] - mx); s += logit[a]; }
    const float inv = 1.f / s;
    #pragma unroll
    for (int a = 0; a < 9; a++) logit[a] *= inv;

    float* hb = hid + ((long)(b * 64 + h * 8)) * HW + pix;
    #pragma unroll 1
    for (int c = 0; c < CHN; c++) {
        float nb[9];
        #pragma unroll
        for (int t = 0; t < 9; t++) nb[t] = sv[c][ly + t / 3][lx + t % 3];
        float o = 0.f;
        #pragma unroll
        for (int a = 0; a < 9; a++) {
            float vv = nb[a] + scb[c * 9 + a];
            #pragma unroll
            for (int t = 0; t < 9; t++)
                vv = fmaf(swt[(c * 9 + a) * 9 + t], nb[t], vv);
            o = fmaf(logit[a], vv, o);
        }
        hb[c * HW] = o;
    }
}

extern "C" void kernel_launch(void* const* d_in, const int* in_sizes, int n_in,
                              void* d_out, int out_size)
{
    const float* x      = (const float*)d_in[0];  // (16,256,56,56)
    const float* qkv_w  = (const float*)d_in[1];  // (192,256)
    const float* qkv_b  = (const float*)d_in[2];  // (192)
    const float* dc_b   = (const float*)d_in[3];  // (72)
    const float* dc1_w  = (const float*)d_in[4];  // (72,1,3,3)
    const float* dc1_b  = (const float*)d_in[5];  // (72)
    const float* rpb    = (const float*)d_in[6];  // (1,8,1,9,1,1)
    const float* proj_w = (const float*)d_in[7];  // (256,64)
    const float* proj_b = (const float*)d_in[8];  // (256)
    float* out = (float*)d_out;                   // (16,256,56,56)

    float *qkv_p, *hid_p;
    cudaGetSymbolAddress((void**)&qkv_p, g_qkv);
    cudaGetSymbolAddress((void**)&hid_p, g_hid);

    // 1) QKV GEMM: (192 x 3136 x 256) per batch
    gemm_bias<<<dim3(HW / 64, 192 / 64, 16), 256>>>(
        qkv_w, x, qkv_b, qkv_p, 192, HW, 256, (long)256 * HW, (long)192 * HW);

    // 2) Fused sliding attention
    attn_kernel<<<dim3(16, NHD, 16), 256>>>(qkv_p, dc_b, dc1_w, dc1_b, rpb, hid_p);

    // 3) Proj GEMM: (256 x 3136 x 64) per batch
    gemm_bias<<<dim3(HW / 64, 256 / 64, 16), 256>>>(
        proj_w, hid_p, proj_b, out, 256, HW, 64, (long)64 * HW, (long)256 * HW);
}

// round 5
// speedup vs baseline: 1.3656x; 1.3656x over previous
#include <cuda_runtime.h>

typedef unsigned long long ull;

#define HW   3136
#define WID  56
#define NHD  8
#define CHN  8
#define SCALE 0.17677669529663687f  // (256/8)^-0.5

// Scratch (alloc-free rule: __device__ globals)
__device__ float g_qkv[16 * 192 * HW];   // (B, 192, H*W)
__device__ float g_hid[16 * 64  * HW];   // (B, 64, H*W)

__device__ __forceinline__ ull pack2(float x) {
    ull r; unsigned u = __float_as_uint(x);
    asm("mov.b64 %0, {%1, %1};" : "=l"(r) : "r"(u));
    return r;
}
__device__ __forceinline__ void fma2(ull &d, ull a, ull b) {
    asm("fma.rn.f32x2 %0, %1, %2, %3;" : "=l"(d) : "l"(a), "l"(b), "l"(d));
}

union F4U { float4 f; ulonglong2 u; };

#define BM 64
#define BN 128
#define BK 16

// ---------------------------------------------------------------------------
// fp32x2 GEMM: C[b,m,n] = sum_k A[m,k] * X[b,k,n] + bias[m]
// 64x128 block tile, BK=16, 128 threads, 8x8 microtile (split 4+4 in m and n),
// packed fma.rn.f32x2, double-buffered smem (1 barrier per k-tile).
// M % 64 == 0, K % 16 == 0; N guarded (N % 4 == 0).
// ---------------------------------------------------------------------------
__global__ void __launch_bounds__(128)
gemm_f32x2(const float* __restrict__ A, const float* __restrict__ X,
           const float* __restrict__ bias, float* __restrict__ C,
           int M, int N, int K, long xbs, long cbs)
{
    __shared__ float sA[2][BK][BM];
    __shared__ float sB[2][BK][BN];
    const int tid = threadIdx.x;
    const int m0 = blockIdx.y * BM;
    const int n0 = blockIdx.x * BN;
    const float* Xb = X + (long)blockIdx.z * xbs;
    float*       Cb = C + (long)blockIdx.z * cbs;

    const int aRow = tid >> 1;           // 0..63
    const int aCol = (tid & 1) << 3;     // 0 or 8
    const int ty   = tid >> 4;           // 0..7
    const int tx   = tid & 15;           // 0..15

    ull acc[8][4];
    #pragma unroll
    for (int i = 0; i < 8; i++)
        #pragma unroll
        for (int j = 0; j < 4; j++) acc[i][j] = 0ULL;

    const float* aPtr = A + (long)(m0 + aRow) * K + aCol;

    float4 aR0, aR1, bR[4];
    // ---- prologue: load tile 0 ----
    aR0 = *(const float4*)(aPtr);
    aR1 = *(const float4*)(aPtr + 4);
    #pragma unroll
    for (int i = 0; i < 4; i++) {
        const int idx = tid + (i << 7);
        const int r = idx >> 5, c = (idx & 31) << 2;
        const int n = n0 + c;
        bR[i] = (n < N) ? *(const float4*)&Xb[(long)r * N + n]
                        : make_float4(0.f, 0.f, 0.f, 0.f);
    }
    sA[0][aCol+0][aRow] = aR0.x; sA[0][aCol+1][aRow] = aR0.y;
    sA[0][aCol+2][aRow] = aR0.z; sA[0][aCol+3][aRow] = aR0.w;
    sA[0][aCol+4][aRow] = aR1.x; sA[0][aCol+5][aRow] = aR1.y;
    sA[0][aCol+6][aRow] = aR1.z; sA[0][aCol+7][aRow] = aR1.w;
    #pragma unroll
    for (int i = 0; i < 4; i++) {
        const int idx = tid + (i << 7);
        const int r = idx >> 5, c = (idx & 31) << 2;
        *(float4*)&sB[0][r][c] = bR[i];
    }
    __syncthreads();

    const int T = K / BK;
    for (int t = 0; t < T; t++) {
        const int cur = t & 1;
        if (t + 1 < T) {   // prefetch next tile into registers
            const int k0 = (t + 1) * BK;
            aR0 = *(const float4*)(aPtr + k0);
            aR1 = *(const float4*)(aPtr + k0 + 4);
            #pragma unroll
            for (int i = 0; i < 4; i++) {
                const int idx = tid + (i << 7);
                const int r = idx >> 5, c = (idx & 31) << 2;
                const int n = n0 + c;
                bR[i] = (n < N) ? *(const float4*)&Xb[(long)(k0 + r) * N + n]
                                : make_float4(0.f, 0.f, 0.f, 0.f);
            }
        }
        #pragma unroll
        for (int k = 0; k < BK; k++) {
            const float4 fa0 = *(const float4*)&sA[cur][k][ty << 2];
            const float4 fa1 = *(const float4*)&sA[cur][k][32 + (ty << 2)];
            F4U B0, B1;
            B0.f = *(const float4*)&sB[cur][k][tx << 2];
            B1.f = *(const float4*)&sB[cur][k][64 + (tx << 2)];
            const ull ad[8] = { pack2(fa0.x), pack2(fa0.y), pack2(fa0.z), pack2(fa0.w),
                                pack2(fa1.x), pack2(fa1.y), pack2(fa1.z), pack2(fa1.w) };
            #pragma unroll
            for (int i = 0; i < 8; i++) {
                fma2(acc[i][0], ad[i], B0.u.x);
                fma2(acc[i][1], ad[i], B0.u.y);
                fma2(acc[i][2], ad[i], B1.u.x);
                fma2(acc[i][3], ad[i], B1.u.y);
            }
        }
        if (t + 1 < T) {
            const int nxt = cur ^ 1;
            sA[nxt][aCol+0][aRow] = aR0.x; sA[nxt][aCol+1][aRow] = aR0.y;
            sA[nxt][aCol+2][aRow] = aR0.z; sA[nxt][aCol+3][aRow] = aR0.w;
            sA[nxt][aCol+4][aRow] = aR1.x; sA[nxt][aCol+5][aRow] = aR1.y;
            sA[nxt][aCol+6][aRow] = aR1.z; sA[nxt][aCol+7][aRow] = aR1.w;
            #pragma unroll
            for (int i = 0; i < 4; i++) {
                const int idx = tid + (i << 7);
                const int r = idx >> 5, c = (idx & 31) << 2;
                *(float4*)&sB[nxt][r][c] = bR[i];
            }
            __syncthreads();
        }
    }

    // ---- epilogue ----
    const bool ok0 = (n0 + (tx << 2)) < N;
    const bool ok1 = (n0 + 64 + (tx << 2)) < N;
    #pragma unroll
    for (int i = 0; i < 8; i++) {
        const int m = m0 + ((i < 4) ? (ty << 2) + i : 32 + (ty << 2) + (i - 4));
        const float bs = bias[m];
        F4U lo, hi;
        lo.u.x = acc[i][0]; lo.u.y = acc[i][1];
        hi.u.x = acc[i][2]; hi.u.y = acc[i][3];
        lo.f.x += bs; lo.f.y += bs; lo.f.z += bs; lo.f.w += bs;
        hi.f.x += bs; hi.f.y += bs; hi.f.z += bs; hi.f.w += bs;
        if (ok0) *(float4*)&Cb[(long)m * N + n0 + (tx << 2)]      = lo.f;
        if (ok1) *(float4*)&Cb[(long)m * N + n0 + 64 + (tx << 2)] = hi.f;
    }
}

// ---------------------------------------------------------------------------
// Fused sliding attention (unchanged from R1). One block = 14x14 pixel tile
// for one (batch, head).
// ---------------------------------------------------------------------------
__global__ void attn_kernel(const float* __restrict__ qkv,
                            const float* __restrict__ dc_b,
                            const float* __restrict__ dc1_w,
                            const float* __restrict__ dc1_b,
                            const float* __restrict__ rpb,
                            float* __restrict__ hid)
{
    __shared__ float sk[CHN][16][16];
    __shared__ float sv[CHN][16][16];
    __shared__ float swt[648];   // dc1_w: (c*9+a)*9 + t
    __shared__ float scb[72];    // dc_b + dc1_b
    __shared__ float srp[9];     // rpb for this head

    const int tid = threadIdx.x;
    const int h = blockIdx.y;
    const int b = blockIdx.z;
    const int tileY = blockIdx.x >> 2, tileX = blockIdx.x & 3;
    const int gy0 = tileY * 14 - 1, gx0 = tileX * 14 - 1;

    for (int i = tid; i < 648; i += 256) swt[i] = dc1_w[i];
    if (tid < 72) scb[tid] = dc_b[tid] + dc1_b[tid];
    if (tid < 9)  srp[tid] = rpb[h * 9 + tid];

    {   // halo load
        const int r = tid >> 4, s = tid & 15;
        const int gy = gy0 + r, gx = gx0 + s;
        const bool ok = (gy >= 0) & (gy < WID) & (gx >= 0) & (gx < WID);
        const int off = ok ? gy * WID + gx : 0;
        const float* kb = qkv + ((long)(b * 192 + h * 24 + 8)) * HW + off;
        #pragma unroll
        for (int c = 0; c < CHN; c++) {
            sk[c][r][s] = ok ? kb[c * HW]       : 0.f;
            sv[c][r][s] = ok ? kb[(8 + c) * HW] : 0.f;
        }
    }
    __syncthreads();

    if (tid >= 196) return;
    const int ly = tid / 14, lx = tid - ly * 14;
    const int gy = tileY * 14 + ly, gx = tileX * 14 + lx;
    const int pix = gy * WID + gx;

    float q[CHN];
    {
        const float* qp = qkv + ((long)(b * 192 + h * 24)) * HW + pix;
        #pragma unroll
        for (int c = 0; c < CHN; c++) q[c] = qp[c * HW] * SCALE;
    }

    float logit[9];
    #pragma unroll
    for (int a = 0; a < 9; a++) logit[a] = 0.f;

    #pragma unroll 1
    for (int c = 0; c < CHN; c++) {
        float nb[9];
        #pragma unroll
        for (int t = 0; t < 9; t++) nb[t] = sk[c][ly + t / 3][lx + t % 3];
        #pragma unroll
        for (int a = 0; a < 9; a++) {
            float kv = nb[a] + scb[c * 9 + a] + srp[a];
            #pragma unroll
            for (int t = 0; t < 9; t++)
                kv = fmaf(swt[(c * 9 + a) * 9 + t], nb[t], kv);
            logit[a] = fmaf(q[c], kv, logit[a]);
        }
    }

    float mx = logit[0];
    #pragma unroll
    for (int a = 1; a < 9; a++) mx = fmaxf(mx, logit[a]);
    float s = 0.f;
    #pragma unroll
    for (int a = 0; a < 9; a++) { logit[a] = __expf(logit[a] - mx); s += logit[a]; }
    const float inv = 1.f / s;
    #pragma unroll
    for (int a = 0; a < 9; a++) logit[a] *= inv;

    float* hb = hid + ((long)(b * 64 + h * 8)) * HW + pix;
    #pragma unroll 1
    for (int c = 0; c < CHN; c++) {
        float nb[9];
        #pragma unroll
        for (int t = 0; t < 9; t++) nb[t] = sv[c][ly + t / 3][lx + t % 3];
        float o = 0.f;
        #pragma unroll
        for (int a = 0; a < 9; a++) {
            float vv = nb[a] + scb[c * 9 + a];
            #pragma unroll
            for (int t = 0; t < 9; t++)
                vv = fmaf(swt[(c * 9 + a) * 9 + t], nb[t], vv);
            o = fmaf(logit[a], vv, o);
        }
        hb[c * HW] = o;
    }
}

extern "C" void kernel_launch(void* const* d_in, const int* in_sizes, int n_in,
                              void* d_out, int out_size)
{
    const float* x      = (const float*)d_in[0];  // (16,256,56,56)
    const float* qkv_w  = (const float*)d_in[1];  // (192,256)
    const float* qkv_b  = (const float*)d_in[2];  // (192)
    const float* dc_b   = (const float*)d_in[3];  // (72)
    const float* dc1_w  = (const float*)d_in[4];  // (72,1,3,3)
    const float* dc1_b  = (const float*)d_in[5];  // (72)
    const float* rpb    = (const float*)d_in[6];  // (1,8,1,9,1,1)
    const float* proj_w = (const float*)d_in[7];  // (256,64)
    const float* proj_b = (const float*)d_in[8];  // (256)
    float* out = (float*)d_out;                   // (16,256,56,56)

    float *qkv_p, *hid_p;
    cudaGetSymbolAddress((void**)&qkv_p, g_qkv);
    cudaGetSymbolAddress((void**)&hid_p, g_hid);

    const int nTiles = (HW + BN - 1) / BN;  // 25

    // 1) QKV GEMM: (192 x 3136 x 256) per batch
    gemm_f32x2<<<dim3(nTiles, 192 / BM, 16), 128>>>(
        qkv_w, x, qkv_b, qkv_p, 192, HW, 256, (long)256 * HW, (long)192 * HW);

    // 2) Fused sliding attention
    attn_kernel<<<dim3(16, NHD, 16), 256>>>(qkv_p, dc_b, dc1_w, dc1_b, rpb, hid_p);

    // 3) Proj GEMM: (256 x 3136 x 64) per batch
    gemm_f32x2<<<dim3(nTiles, 256 / BM, 16), 128>>>(
        proj_w, hid_p, proj_b, out, 256, HW, 64, (long)64 * HW, (long)256 * HW);
}

// round 6
// speedup vs baseline: 1.7435x; 1.2767x over previous
#include <cuda_runtime.h>

typedef unsigned long long ull;

#define HW   3136
#define WID  56
#define NHD  8
#define CHN  8
#define SCALE 0.17677669529663687f  // (256/8)^-0.5

// Scratch (alloc-free rule: __device__ globals)
__device__ float g_qkv[16 * 192 * HW];   // (B, 192, H*W)
__device__ float g_hid[16 * 64  * HW];   // (B, 64, H*W)

__device__ __forceinline__ ull pack2(float x) {
    ull r; unsigned u = __float_as_uint(x);
    asm("mov.b64 %0, {%1, %1};" : "=l"(r) : "r"(u));
    return r;
}
__device__ __forceinline__ ull pack2f(float a, float b) {
    ull r;
    asm("mov.b64 %0, {%1, %2};" : "=l"(r) : "f"(a), "f"(b));
    return r;
}
__device__ __forceinline__ void unpack2(ull v, float &a, float &b) {
    asm("mov.b64 {%0, %1}, %2;" : "=f"(a), "=f"(b) : "l"(v));
}
__device__ __forceinline__ void fma2(ull &d, ull a, ull b) {
    asm("fma.rn.f32x2 %0, %1, %2, %3;" : "=l"(d) : "l"(a), "l"(b), "l"(d));
}

union F4U { float4 f; ulonglong2 u; };

#define BM 64
#define BN 128
#define BK 16

// ---------------------------------------------------------------------------
// fp32x2 GEMM (unchanged from R5): C[b,m,n] = sum_k A[m,k]*X[b,k,n] + bias[m]
// ---------------------------------------------------------------------------
__global__ void __launch_bounds__(128)
gemm_f32x2(const float* __restrict__ A, const float* __restrict__ X,
           const float* __restrict__ bias, float* __restrict__ C,
           int M, int N, int K, long xbs, long cbs)
{
    __shared__ float sA[2][BK][BM];
    __shared__ float sB[2][BK][BN];
    const int tid = threadIdx.x;
    const int m0 = blockIdx.y * BM;
    const int n0 = blockIdx.x * BN;
    const float* Xb = X + (long)blockIdx.z * xbs;
    float*       Cb = C + (long)blockIdx.z * cbs;

    const int aRow = tid >> 1;
    const int aCol = (tid & 1) << 3;
    const int ty   = tid >> 4;
    const int tx   = tid & 15;

    ull acc[8][4];
    #pragma unroll
    for (int i = 0; i < 8; i++)
        #pragma unroll
        for (int j = 0; j < 4; j++) acc[i][j] = 0ULL;

    const float* aPtr = A + (long)(m0 + aRow) * K + aCol;

    float4 aR0, aR1, bR[4];
    aR0 = *(const float4*)(aPtr);
    aR1 = *(const float4*)(aPtr + 4);
    #pragma unroll
    for (int i = 0; i < 4; i++) {
        const int idx = tid + (i << 7);
        const int r = idx >> 5, c = (idx & 31) << 2;
        const int n = n0 + c;
        bR[i] = (n < N) ? *(const float4*)&Xb[(long)r * N + n]
                        : make_float4(0.f, 0.f, 0.f, 0.f);
    }
    sA[0][aCol+0][aRow] = aR0.x; sA[0][aCol+1][aRow] = aR0.y;
    sA[0][aCol+2][aRow] = aR0.z; sA[0][aCol+3][aRow] = aR0.w;
    sA[0][aCol+4][aRow] = aR1.x; sA[0][aCol+5][aRow] = aR1.y;
    sA[0][aCol+6][aRow] = aR1.z; sA[0][aCol+7][aRow] = aR1.w;
    #pragma unroll
    for (int i = 0; i < 4; i++) {
        const int idx = tid + (i << 7);
        const int r = idx >> 5, c = (idx & 31) << 2;
        *(float4*)&sB[0][r][c] = bR[i];
    }
    __syncthreads();

    const int T = K / BK;
    for (int t = 0; t < T; t++) {
        const int cur = t & 1;
        if (t + 1 < T) {
            const int k0 = (t + 1) * BK;
            aR0 = *(const float4*)(aPtr + k0);
            aR1 = *(const float4*)(aPtr + k0 + 4);
            #pragma unroll
            for (int i = 0; i < 4; i++) {
                const int idx = tid + (i << 7);
                const int r = idx >> 5, c = (idx & 31) << 2;
                const int n = n0 + c;
                bR[i] = (n < N) ? *(const float4*)&Xb[(long)(k0 + r) * N + n]
                                : make_float4(0.f, 0.f, 0.f, 0.f);
            }
        }
        #pragma unroll
        for (int k = 0; k < BK; k++) {
            const float4 fa0 = *(const float4*)&sA[cur][k][ty << 2];
            const float4 fa1 = *(const float4*)&sA[cur][k][32 + (ty << 2)];
            F4U B0, B1;
            B0.f = *(const float4*)&sB[cur][k][tx << 2];
            B1.f = *(const float4*)&sB[cur][k][64 + (tx << 2)];
            const ull ad[8] = { pack2(fa0.x), pack2(fa0.y), pack2(fa0.z), pack2(fa0.w),
                                pack2(fa1.x), pack2(fa1.y), pack2(fa1.z), pack2(fa1.w) };
            #pragma unroll
            for (int i = 0; i < 8; i++) {
                fma2(acc[i][0], ad[i], B0.u.x);
                fma2(acc[i][1], ad[i], B0.u.y);
                fma2(acc[i][2], ad[i], B1.u.x);
                fma2(acc[i][3], ad[i], B1.u.y);
            }
        }
        if (t + 1 < T) {
            const int nxt = cur ^ 1;
            sA[nxt][aCol+0][aRow] = aR0.x; sA[nxt][aCol+1][aRow] = aR0.y;
            sA[nxt][aCol+2][aRow] = aR0.z; sA[nxt][aCol+3][aRow] = aR0.w;
            sA[nxt][aCol+4][aRow] = aR1.x; sA[nxt][aCol+5][aRow] = aR1.y;
            sA[nxt][aCol+6][aRow] = aR1.z; sA[nxt][aCol+7][aRow] = aR1.w;
            #pragma unroll
            for (int i = 0; i < 4; i++) {
                const int idx = tid + (i << 7);
                const int r = idx >> 5, c = (idx & 31) << 2;
                *(float4*)&sB[nxt][r][c] = bR[i];
            }
            __syncthreads();
        }
    }

    const bool ok0 = (n0 + (tx << 2)) < N;
    const bool ok1 = (n0 + 64 + (tx << 2)) < N;
    #pragma unroll
    for (int i = 0; i < 8; i++) {
        const int m = m0 + ((i < 4) ? (ty << 2) + i : 32 + (ty << 2) + (i - 4));
        const float bs = bias[m];
        F4U lo, hi;
        lo.u.x = acc[i][0]; lo.u.y = acc[i][1];
        hi.u.x = acc[i][2]; hi.u.y = acc[i][3];
        lo.f.x += bs; lo.f.y += bs; lo.f.z += bs; lo.f.w += bs;
        hi.f.x += bs; hi.f.y += bs; hi.f.z += bs; hi.f.w += bs;
        if (ok0) *(float4*)&Cb[(long)m * N + n0 + (tx << 2)]      = lo.f;
        if (ok1) *(float4*)&Cb[(long)m * N + n0 + 64 + (tx << 2)] = hi.f;
    }
}

// ---------------------------------------------------------------------------
// Fused sliding attention v2: 2 pixels/thread, packed fma.rn.f32x2,
// pre-duplicated packed weights in smem (identity tap folded in).
// Block = 56x8 pixel tile for one (batch, head); 224 threads (28x8).
// ---------------------------------------------------------------------------
#define AT_ROWS 8
#define AT_HROW (AT_ROWS + 2)

__global__ void __launch_bounds__(224)
attn2(const float* __restrict__ qkv,
      const float* __restrict__ dc_b,
      const float* __restrict__ dc1_w,
      const float* __restrict__ dc1_b,
      const float* __restrict__ rpb,
      float* __restrict__ hid)
{
    __shared__ float sk[CHN][AT_HROW][58];
    __shared__ float sv[CHN][AT_HROW][58];
    __shared__ ull   wp[72][10];   // packed (w,w); [ca][t], t<9, identity folded
    __shared__ ull   bk2[72];      // packed k bias: dc_b+dc1_b+rpb
    __shared__ ull   bv2[72];      // packed v bias: dc_b+dc1_b

    const int tid = threadIdx.x;
    const int h = blockIdx.y;
    const int b = blockIdx.z;
    const int y0 = blockIdx.x * AT_ROWS;

    // ---- build packed weights (once per block) ----
    if (tid < 72) {
        const int a = tid - (tid / 9) * 9;
        const float cb = dc_b[tid] + dc1_b[tid];
        bv2[tid] = pack2(cb);
        bk2[tid] = pack2(cb + rpb[h * 9 + a]);
        #pragma unroll
        for (int t = 0; t < 9; t++) {
            float w = dc1_w[tid * 9 + t] + ((t == a) ? 1.f : 0.f);
            wp[tid][t] = pack2(w);
        }
        wp[tid][9] = 0ULL;
    }

    // ---- halo load: 10 rows x 58 cols x 8 channels, k and v ----
    {
        const float* base = qkv + ((long)(b * 192 + h * 24 + 8)) * HW;
        for (int i = tid; i < AT_HROW * 58; i += 224) {
            const int r = i / 58, s = i - r * 58;
            const int gy = y0 - 1 + r, gx = s - 1;
            const bool ok = (gy >= 0) & (gy < WID) & (gx >= 0) & (gx < WID);
            const int off = ok ? gy * WID + gx : 0;
            #pragma unroll
            for (int c = 0; c < CHN; c++) {
                sk[c][r][s] = ok ? base[c * HW + off]       : 0.f;
                sv[c][r][s] = ok ? base[(8 + c) * HW + off] : 0.f;
            }
        }
    }

    // ---- q prefetch (global, overlaps barrier) ----
    const int tx  = tid % 28;          // 0..27
    const int tyy = tid / 28;          // 0..7
    const int px0 = tx * 2;
    const int gy  = y0 + tyy;          // always < 56
    const int pix = gy * WID + px0;

    ull q2[CHN];
    {
        const float* qp = qkv + ((long)(b * 192 + h * 24)) * HW + pix;
        #pragma unroll
        for (int c = 0; c < CHN; c++) {
            const float2 qv = *(const float2*)(qp + (long)c * HW);
            q2[c] = pack2f(qv.x * SCALE, qv.y * SCALE);
        }
    }
    __syncthreads();

    // ---- K phase: logits ----
    ull logit2[9];
    #pragma unroll
    for (int a = 0; a < 9; a++) logit2[a] = 0ULL;

    #pragma unroll 1
    for (int c = 0; c < CHN; c++) {
        ull nb[9];
        #pragma unroll
        for (int dy = 0; dy < 3; dy++) {
            const float* rp = &sk[c][tyy + dy][px0];
            const ull A  = *(const ull*)rp;
            const ull Cc = *(const ull*)(rp + 2);
            nb[dy * 3 + 0] = A;
            nb[dy * 3 + 1] = (A >> 32) | (Cc << 32);
            nb[dy * 3 + 2] = Cc;
        }
        #pragma unroll
        for (int a = 0; a < 9; a++) {
            const int ca = c * 9 + a;
            const ulonglong2 w01 = *(const ulonglong2*)&wp[ca][0];
            const ulonglong2 w23 = *(const ulonglong2*)&wp[ca][2];
            const ulonglong2 w45 = *(const ulonglong2*)&wp[ca][4];
            const ulonglong2 w67 = *(const ulonglong2*)&wp[ca][6];
            const ulonglong2 w8p = *(const ulonglong2*)&wp[ca][8];
            ull kv = bk2[ca];
            fma2(kv, w01.x, nb[0]); fma2(kv, w01.y, nb[1]);
            fma2(kv, w23.x, nb[2]); fma2(kv, w23.y, nb[3]);
            fma2(kv, w45.x, nb[4]); fma2(kv, w45.y, nb[5]);
            fma2(kv, w67.x, nb[6]); fma2(kv, w67.y, nb[7]);
            fma2(kv, w8p.x, nb[8]);
            fma2(logit2[a], q2[c], kv);
        }
    }

    // ---- softmax (scalar, both pixels) ----
    ull p2[9];
    {
        float l0[9], l1[9];
        #pragma unroll
        for (int a = 0; a < 9; a++) unpack2(logit2[a], l0[a], l1[a]);
        float m0 = l0[0], m1 = l1[0];
        #pragma unroll
        for (int a = 1; a < 9; a++) { m0 = fmaxf(m0, l0[a]); m1 = fmaxf(m1, l1[a]); }
        float s0 = 0.f, s1 = 0.f;
        #pragma unroll
        for (int a = 0; a < 9; a++) {
            l0[a] = __expf(l0[a] - m0); s0 += l0[a];
            l1[a] = __expf(l1[a] - m1); s1 += l1[a];
        }
        const float i0 = 1.f / s0, i1 = 1.f / s1;
        #pragma unroll
        for (int a = 0; a < 9; a++) p2[a] = pack2f(l0[a] * i0, l1[a] * i1);
    }

    // ---- V phase: output ----
    float* hb = hid + ((long)(b * 64 + h * 8)) * HW + pix;
    #pragma unroll 1
    for (int c = 0; c < CHN; c++) {
        ull nb[9];
        #pragma unroll
        for (int dy = 0; dy < 3; dy++) {
            const float* rp = &sv[c][tyy + dy][px0];
            const ull A  = *(const ull*)rp;
            const ull Cc = *(const ull*)(rp + 2);
            nb[dy * 3 + 0] = A;
            nb[dy * 3 + 1] = (A >> 32) | (Cc << 32);
            nb[dy * 3 + 2] = Cc;
        }
        ull o2 = 0ULL;
        #pragma unroll
        for (int a = 0; a < 9; a++) {
            const int ca = c * 9 + a;
            const ulonglong2 w01 = *(const ulonglong2*)&wp[ca][0];
            const ulonglong2 w23 = *(const ulonglong2*)&wp[ca][2];
            const ulonglong2 w45 = *(const ulonglong2*)&wp[ca][4];
            const ulonglong2 w67 = *(const ulonglong2*)&wp[ca][6];
            const ulonglong2 w8p = *(const ulonglong2*)&wp[ca][8];
            ull vv = bv2[ca];
            fma2(vv, w01.x, nb[0]); fma2(vv, w01.y, nb[1]);
            fma2(vv, w23.x, nb[2]); fma2(vv, w23.y, nb[3]);
            fma2(vv, w45.x, nb[4]); fma2(vv, w45.y, nb[5]);
            fma2(vv, w67.x, nb[6]); fma2(vv, w67.y, nb[7]);
            fma2(vv, w8p.x, nb[8]);
            fma2(o2, p2[a], vv);
        }
        float o0, o1; unpack2(o2, o0, o1);
        *(float2*)(hb + (long)c * HW) = make_float2(o0, o1);
    }
}

extern "C" void kernel_launch(void* const* d_in, const int* in_sizes, int n_in,
                              void* d_out, int out_size)
{
    const float* x      = (const float*)d_in[0];  // (16,256,56,56)
    const float* qkv_w  = (const float*)d_in[1];  // (192,256)
    const float* qkv_b  = (const float*)d_in[2];  // (192)
    const float* dc_b   = (const float*)d_in[3];  // (72)
    const float* dc1_w  = (const float*)d_in[4];  // (72,1,3,3)
    const float* dc1_b  = (const float*)d_in[5];  // (72)
    const float* rpb    = (const float*)d_in[6];  // (1,8,1,9,1,1)
    const float* proj_w = (const float*)d_in[7];  // (256,64)
    const float* proj_b = (const float*)d_in[8];  // (256)
    float* out = (float*)d_out;                   // (16,256,56,56)

    float *qkv_p, *hid_p;
    cudaGetSymbolAddress((void**)&qkv_p, g_qkv);
    cudaGetSymbolAddress((void**)&hid_p, g_hid);

    const int nTiles = (HW + BN - 1) / BN;  // 25

    // 1) QKV GEMM: (192 x 3136 x 256) per batch
    gemm_f32x2<<<dim3(nTiles, 192 / BM, 16), 128>>>(
        qkv_w, x, qkv_b, qkv_p, 192, HW, 256, (long)256 * HW, (long)192 * HW);

    // 2) Fused sliding attention (56x8 tiles, 7 per column)
    attn2<<<dim3(WID / AT_ROWS, NHD, 16), 224>>>(
        qkv_p, dc_b, dc1_w, dc1_b, rpb, hid_p);

    // 3) Proj GEMM: (256 x 3136 x 64) per batch
    gemm_f32x2<<<dim3(nTiles, 256 / BM, 16), 128>>>(
        proj_w, hid_p, proj_b, out, 256, HW, 64, (long)64 * HW, (long)256 * HW);
}

// round 10
// speedup vs baseline: 2.2621x; 1.2975x over previous
#include <cuda_runtime.h>
#include <cuda_bf16.h>
#include <cstdint>

typedef unsigned long long ull;

#define HW   3136
#define WID  56
#define NHD  8
#define CHN  8
#define SCALE 0.17677669529663687f  // (256/8)^-0.5

// Scratch (alloc-free rule: __device__ globals)
__device__ float g_qkv[16 * 192 * HW];   // (B, 192, H*W)
__device__ float g_hid[16 * 64  * HW];   // (B, 64, H*W)

// ---------------------------------------------------------------------------
// helpers
// ---------------------------------------------------------------------------
__device__ __forceinline__ ull pack2(float x) {
    ull r; unsigned u = __float_as_uint(x);
    asm("mov.b64 %0, {%1, %1};" : "=l"(r) : "r"(u));
    return r;
}
__device__ __forceinline__ ull pack2f(float a, float b) {
    ull r;
    asm("mov.b64 %0, {%1, %2};" : "=l"(r) : "f"(a), "f"(b));
    return r;
}
__device__ __forceinline__ void unpack2(ull v, float &a, float &b) {
    asm("mov.b64 {%0, %1}, %2;" : "=f"(a), "=f"(b) : "l"(v));
}
__device__ __forceinline__ void fma2(ull &d, ull a, ull b) {
    asm("fma.rn.f32x2 %0, %1, %2, %3;" : "=l"(d) : "l"(a), "l"(b), "l"(d));
}
__device__ __forceinline__ uint32_t smem_u32(const void* p) {
    uint32_t a;
    asm("{ .reg .u64 t; cvta.to.shared.u64 t, %1; cvt.u32.u64 %0, t; }"
        : "=r"(a) : "l"(p));
    return a;
}
// bf16 split: (x,y) -> packed hi bf16x2 (x low half) and lo bf16x2
__device__ __forceinline__ void split2(float x, float y, unsigned &hi2, unsigned &lo2) {
    __nv_bfloat16 xh = __float2bfloat16_rn(x);
    __nv_bfloat16 yh = __float2bfloat16_rn(y);
    float xr = x - __bfloat162float(xh);
    float yr = y - __bfloat162float(yh);
    __nv_bfloat162 h2 = __halves2bfloat162(xh, yh);
    __nv_bfloat162 l2 = __halves2bfloat162(__float2bfloat16_rn(xr), __float2bfloat16_rn(yr));
    hi2 = *reinterpret_cast<unsigned*>(&h2);
    lo2 = *reinterpret_cast<unsigned*>(&l2);
}
__device__ __forceinline__ void ldsm4(uint32_t (&r)[4], uint32_t addr) {
    asm volatile("ldmatrix.sync.aligned.m8n8.x4.shared.b16 {%0,%1,%2,%3}, [%4];"
        : "=r"(r[0]), "=r"(r[1]), "=r"(r[2]), "=r"(r[3]) : "r"(addr));
}
__device__ __forceinline__ void mma16816(float (&d)[4], const uint32_t (&a)[4],
                                         uint32_t b0, uint32_t b1) {
    asm volatile(
        "mma.sync.aligned.m16n8k16.row.col.f32.bf16.bf16.f32 "
        "{%0,%1,%2,%3}, {%4,%5,%6,%7}, {%8,%9}, {%0,%1,%2,%3};"
        : "+f"(d[0]), "+f"(d[1]), "+f"(d[2]), "+f"(d[3])
        : "r"(a[0]), "r"(a[1]), "r"(a[2]), "r"(a[3]), "r"(b0), "r"(b1));
}
__device__ __forceinline__ void sts128(uint32_t addr, unsigned a, unsigned b,
                                       unsigned c, unsigned d) {
    asm volatile("st.shared.v4.b32 [%0], {%1,%2,%3,%4};"
                 :: "r"(addr), "r"(a), "r"(b), "r"(c), "r"(d));
}

// ---------------------------------------------------------------------------
// HMMA bf16x3 GEMM:  C[b, ch, pix] = sum_k W[ch,k] * X[b,k,pix] + bias[ch]
// Block: 128 pixels x NTILE channels. 256 threads = 8 warps (4 m-warps x 2 n).
// A = X^T tile [128 pix][32 k] bf16 hi/lo in smem (80B row stride, conflict-
// free); B = W tile [NTILE ch][32 k] hi/lo. mma.m16n8k16 row.col, 3 MMAs per
// fragment pair (hi*hi + hi*lo + lo*hi), fp32 accum. Double-buffered.
// ---------------------------------------------------------------------------
template<int NTILE, int KTOT>
__global__ void __launch_bounds__(256, 2)
gemm_hmma(const float* __restrict__ X, const float* __restrict__ W,
          const float* __restrict__ bias, float* __restrict__ C)
{
    constexpr int KT    = KTOT / 32;        // k-tiles
    constexpr int WN    = NTILE / 2;        // warp n extent
    constexpr int NFRAG = WN / 8;           // n8 fragments per warp
    constexpr int NPAIR = NFRAG / 2;
    constexpr int ABUF  = 2 * 128 * 80;     // hi+lo, one buffer
    constexpr int BROW  = NTILE * 80;
    constexpr int BBUF  = 2 * BROW;
    constexpr int BOFF  = 2 * ABUF;         // B region start

    extern __shared__ char dyn[];
    const uint32_t sb = smem_u32(dyn);

    const int tid  = threadIdx.x;
    const int wid  = tid >> 5;
    const int lane = tid & 31;
    const int wm   = wid & 3;               // m-warp 0..3
    const int wn   = wid >> 2;              // n-warp 0..1
    const int m0   = blockIdx.x * 128;
    const int n0   = blockIdx.y * NTILE;
    const int b    = blockIdx.z;

    const float* Xb = X + (long)b * KTOT * HW;
    float*       Cb = C + (long)b * gridDim.y * NTILE * HW;

    // loader roles
    const int px    = tid & 127;            // pixel within tile
    const int khx   = tid >> 7;             // k-half (0/1) for X loader
    const int pixg  = min(m0 + px, HW - 1);
    const bool wAct = tid < NTILE * 2;
    const int wch   = tid >> 1;             // channel for W loader
    const int khw   = tid & 1;              // k-half for W loader

    float acc[2][NFRAG][4];
    #pragma unroll
    for (int i = 0; i < 2; i++)
        #pragma unroll
        for (int j = 0; j < NFRAG; j++)
            #pragma unroll
            for (int e = 0; e < 4; e++) acc[i][j][e] = 0.f;

    float xv[16];
    float4 wv[4];

    auto loadRegs = [&](int t) {
        const int kx = t * 32 + khx * 16;
        #pragma unroll
        for (int j = 0; j < 16; j++)
            xv[j] = Xb[(long)(kx + j) * HW + pixg];
        if (wAct) {
            const long wbase = (long)(n0 + wch) * KTOT + t * 32 + khw * 16;
            #pragma unroll
            for (int j = 0; j < 4; j++)
                wv[j] = *(const float4*)(W + wbase + 4 * j);
        }
    };
    auto stsTile = [&](int buf) {
        // X: 16 k values -> 8 pairs -> 2x STS.128 (hi) + 2x (lo)
        const uint32_t Ahi = sb + buf * ABUF;
        const uint32_t Alo = Ahi + 128 * 80;
        #pragma unroll
        for (int g = 0; g < 2; g++) {
            unsigned h[4], l[4];
            #pragma unroll
            for (int k2 = 0; k2 < 4; k2++)
                split2(xv[g * 8 + 2 * k2], xv[g * 8 + 2 * k2 + 1], h[k2], l[k2]);
            const uint32_t off = (uint32_t)(px * 80 + khx * 32 + g * 16);
            sts128(Ahi + off, h[0], h[1], h[2], h[3]);
            sts128(Alo + off, l[0], l[1], l[2], l[3]);
        }
        if (wAct) {
            const uint32_t Bhi = sb + BOFF + buf * BBUF;
            const uint32_t Blo = Bhi + BROW;
            const float wf[16] = { wv[0].x, wv[0].y, wv[0].z, wv[0].w,
                                   wv[1].x, wv[1].y, wv[1].z, wv[1].w,
                                   wv[2].x, wv[2].y, wv[2].z, wv[2].w,
                                   wv[3].x, wv[3].y, wv[3].z, wv[3].w };
            #pragma unroll
            for (int g = 0; g < 2; g++) {
                unsigned h[4], l[4];
                #pragma unroll
                for (int k2 = 0; k2 < 4; k2++)
                    split2(wf[g * 8 + 2 * k2], wf[g * 8 + 2 * k2 + 1], h[k2], l[k2]);
                const uint32_t off = (uint32_t)(wch * 80 + khw * 32 + g * 16);
                sts128(Bhi + off, h[0], h[1], h[2], h[3]);
                sts128(Blo + off, l[0], l[1], l[2], l[3]);
            }
        }
    };
    auto compute = [&](int buf) {
        const uint32_t Ahi = sb + buf * ABUF;
        const uint32_t Alo = Ahi + 128 * 80;
        const uint32_t Bhi = sb + BOFF + buf * BBUF;
        const uint32_t Blo = Bhi + BROW;
        const int lrow = lane & 15;
        const uint32_t kb0 = (uint32_t)((lane >> 4) << 4);   // +16B for hi-k lanes
        #pragma unroll
        for (int s = 0; s < 2; s++) {
            const uint32_t kb = kb0 + 32 * s;
            uint32_t ah[2][4], al[2][4];
            #pragma unroll
            for (int mf = 0; mf < 2; mf++) {
                const uint32_t ro = (uint32_t)((wm * 32 + mf * 16 + lrow) * 80) + kb;
                ldsm4(ah[mf], Ahi + ro);
                ldsm4(al[mf], Alo + ro);
            }
            #pragma unroll
            for (int j = 0; j < NPAIR; j++) {
                const uint32_t ro = (uint32_t)((wn * WN + j * 16 + lrow) * 80) + kb;
                uint32_t bh[4], bl[4];
                ldsm4(bh, Bhi + ro);
                ldsm4(bl, Blo + ro);
                #pragma unroll
                for (int mf = 0; mf < 2; mf++) {
                    mma16816(acc[mf][2*j],   ah[mf], bh[0], bh[2]);
                    mma16816(acc[mf][2*j],   ah[mf], bl[0], bl[2]);
                    mma16816(acc[mf][2*j],   al[mf], bh[0], bh[2]);
                    mma16816(acc[mf][2*j+1], ah[mf], bh[1], bh[3]);
                    mma16816(acc[mf][2*j+1], ah[mf], bl[1], bl[3]);
                    mma16816(acc[mf][2*j+1], al[mf], bh[1], bh[3]);
                }
            }
        }
    };

    // ---- pipeline ----
    loadRegs(0);
    stsTile(0);
    __syncthreads();
    for (int t = 0; t < KT; t++) {
        if (t + 1 < KT) loadRegs(t + 1);
        compute(t & 1);
        if (t + 1 < KT) {
            stsTile((t + 1) & 1);
            __syncthreads();
        }
    }

    // ---- epilogue ----
    const int r0 = lane >> 2;
    const int c0 = 2 * (lane & 3);
    #pragma unroll
    for (int nf = 0; nf < NFRAG; nf++) {
        const int ch = n0 + wn * WN + nf * 8 + c0;
        const float b0 = bias[ch], b1 = bias[ch + 1];
        float* p0 = Cb + (long)ch * HW;
        float* p1 = p0 + HW;
        #pragma unroll
        for (int mf = 0; mf < 2; mf++) {
            const int pr = m0 + wm * 32 + mf * 16 + r0;
            if (pr < HW) {
                p0[pr] = acc[mf][nf][0] + b0;
                p1[pr] = acc[mf][nf][1] + b1;
            }
            if (pr + 8 < HW) {
                p0[pr + 8] = acc[mf][nf][2] + b0;
                p1[pr + 8] = acc[mf][nf][3] + b1;
            }
        }
    }
}

// ---------------------------------------------------------------------------
// Fused sliding attention v2 (unchanged from R6)
// ---------------------------------------------------------------------------
#define AT_ROWS 8
#define AT_HROW (AT_ROWS + 2)

__global__ void __launch_bounds__(224)
attn2(const float* __restrict__ qkv,
      const float* __restrict__ dc_b,
      const float* __restrict__ dc1_w,
      const float* __restrict__ dc1_b,
      const float* __restrict__ rpb,
      float* __restrict__ hid)
{
    __shared__ float sk[CHN][AT_HROW][58];
    __shared__ float sv[CHN][AT_HROW][58];
    __shared__ ull   wp[72][10];
    __shared__ ull   bk2[72];
    __shared__ ull   bv2[72];

    const int tid = threadIdx.x;
    const int h = blockIdx.y;
    const int b = blockIdx.z;
    const int y0 = blockIdx.x * AT_ROWS;

    if (tid < 72) {
        const int a = tid - (tid / 9) * 9;
        const float cb = dc_b[tid] + dc1_b[tid];
        bv2[tid] = pack2(cb);
        bk2[tid] = pack2(cb + rpb[h * 9 + a]);
        #pragma unroll
        for (int t = 0; t < 9; t++) {
            float w = dc1_w[tid * 9 + t] + ((t == a) ? 1.f : 0.f);
            wp[tid][t] = pack2(w);
        }
        wp[tid][9] = 0ULL;
    }

    {
        const float* base = qkv + ((long)(b * 192 + h * 24 + 8)) * HW;
        for (int i = tid; i < AT_HROW * 58; i += 224) {
            const int r = i / 58, s = i - r * 58;
            const int gy = y0 - 1 + r, gx = s - 1;
            const bool ok = (gy >= 0) & (gy < WID) & (gx >= 0) & (gx < WID);
            const int off = ok ? gy * WID + gx : 0;
            #pragma unroll
            for (int c = 0; c < CHN; c++) {
                sk[c][r][s] = ok ? base[c * HW + off]       : 0.f;
                sv[c][r][s] = ok ? base[(8 + c) * HW + off] : 0.f;
            }
        }
    }

    const int tx  = tid % 28;
    const int tyy = tid / 28;
    const int px0 = tx * 2;
    const int gy  = y0 + tyy;
    const int pix = gy * WID + px0;

    ull q2[CHN];
    {
        const float* qp = qkv + ((long)(b * 192 + h * 24)) * HW + pix;
        #pragma unroll
        for (int c = 0; c < CHN; c++) {
            const float2 qv = *(const float2*)(qp + (long)c * HW);
            q2[c] = pack2f(qv.x * SCALE, qv.y * SCALE);
        }
    }
    __syncthreads();

    ull logit2[9];
    #pragma unroll
    for (int a = 0; a < 9; a++) logit2[a] = 0ULL;

    #pragma unroll 1
    for (int c = 0; c < CHN; c++) {
        ull nb[9];
        #pragma unroll
        for (int dy = 0; dy < 3; dy++) {
            const float* rp = &sk[c][tyy + dy][px0];
            const ull A  = *(const ull*)rp;
            const ull Cc = *(const ull*)(rp + 2);
            nb[dy * 3 + 0] = A;
            nb[dy * 3 + 1] = (A >> 32) | (Cc << 32);
            nb[dy * 3 + 2] = Cc;
        }
        #pragma unroll
        for (int a = 0; a < 9; a++) {
            const int ca = c * 9 + a;
            const ulonglong2 w01 = *(const ulonglong2*)&wp[ca][0];
            const ulonglong2 w23 = *(const ulonglong2*)&wp[ca][2];
            const ulonglong2 w45 = *(const ulonglong2*)&wp[ca][4];
            const ulonglong2 w67 = *(const ulonglong2*)&wp[ca][6];
            const ulonglong2 w8p = *(const ulonglong2*)&wp[ca][8];
            ull kv = bk2[ca];
            fma2(kv, w01.x, nb[0]); fma2(kv, w01.y, nb[1]);
            fma2(kv, w23.x, nb[2]); fma2(kv, w23.y, nb[3]);
            fma2(kv, w45.x, nb[4]); fma2(kv, w45.y, nb[5]);
            fma2(kv, w67.x, nb[6]); fma2(kv, w67.y, nb[7]);
            fma2(kv, w8p.x, nb[8]);
            fma2(logit2[a], q2[c], kv);
        }
    }

    ull p2[9];
    {
        float l0[9], l1[9];
        #pragma unroll
        for (int a = 0; a < 9; a++) unpack2(logit2[a], l0[a], l1[a]);
        float m0 = l0[0], m1 = l1[0];
        #pragma unroll
        for (int a = 1; a < 9; a++) { m0 = fmaxf(m0, l0[a]); m1 = fmaxf(m1, l1[a]); }
        float s0 = 0.f, s1 = 0.f;
        #pragma unroll
        for (int a = 0; a < 9; a++) {
            l0[a] = __expf(l0[a] - m0); s0 += l0[a];
            l1[a] = __expf(l1[a] - m1); s1 += l1[a];
        }
        const float i0 = 1.f / s0, i1 = 1.f / s1;
        #pragma unroll
        for (int a = 0; a < 9; a++) p2[a] = pack2f(l0[a] * i0, l1[a] * i1);
    }

    float* hb = hid + ((long)(b * 64 + h * 8)) * HW + pix;
    #pragma unroll 1
    for (int c = 0; c < CHN; c++) {
        ull nb[9];
        #pragma unroll
        for (int dy = 0; dy < 3; dy++) {
            const float* rp = &sv[c][tyy + dy][px0];
            const ull A  = *(const ull*)rp;
            const ull Cc = *(const ull*)(rp + 2);
            nb[dy * 3 + 0] = A;
            nb[dy * 3 + 1] = (A >> 32) | (Cc << 32);
            nb[dy * 3 + 2] = Cc;
        }
        ull o2 = 0ULL;
        #pragma unroll
        for (int a = 0; a < 9; a++) {
            const int ca = c * 9 + a;
            const ulonglong2 w01 = *(const ulonglong2*)&wp[ca][0];
            const ulonglong2 w23 = *(const ulonglong2*)&wp[ca][2];
            const ulonglong2 w45 = *(const ulonglong2*)&wp[ca][4];
            const ulonglong2 w67 = *(const ulonglong2*)&wp[ca][6];
            const ulonglong2 w8p = *(const ulonglong2*)&wp[ca][8];
            ull vv = bv2[ca];
            fma2(vv, w01.x, nb[0]); fma2(vv, w01.y, nb[1]);
            fma2(vv, w23.x, nb[2]); fma2(vv, w23.y, nb[3]);
            fma2(vv, w45.x, nb[4]); fma2(vv, w45.y, nb[5]);
            fma2(vv, w67.x, nb[6]); fma2(vv, w67.y, nb[7]);
            fma2(vv, w8p.x, nb[8]);
            fma2(o2, p2[a], vv);
        }
        float o0, o1; unpack2(o2, o0, o1);
        *(float2*)(hb + (long)c * HW) = make_float2(o0, o1);
    }
}

extern "C" void kernel_launch(void* const* d_in, const int* in_sizes, int n_in,
                              void* d_out, int out_size)
{
    const float* x      = (const float*)d_in[0];  // (16,256,56,56)
    const float* qkv_w  = (const float*)d_in[1];  // (192,256)
    const float* qkv_b  = (const float*)d_in[2];  // (192)
    const float* dc_b   = (const float*)d_in[3];  // (72)
    const float* dc1_w  = (const float*)d_in[4];  // (72,1,3,3)
    const float* dc1_b  = (const float*)d_in[5];  // (72)
    const float* rpb    = (const float*)d_in[6];  // (1,8,1,9,1,1)
    const float* proj_w = (const float*)d_in[7];  // (256,64)
    const float* proj_b = (const float*)d_in[8];  // (256)
    float* out = (float*)d_out;                   // (16,256,56,56)

    float *qkv_p, *hid_p;
    cudaGetSymbolAddress((void**)&qkv_p, g_qkv);
    cudaGetSymbolAddress((void**)&hid_p, g_hid);

    // dynamic smem: A buffers 40960 + B buffers
    const int SMEM_QKV  = 2 * (2 * 128 * 80) + 2 * (2 * 96 * 80);   // 71,680
    const int SMEM_PROJ = 2 * (2 * 128 * 80) + 2 * (2 * 128 * 80);  // 81,920
    cudaFuncSetAttribute(gemm_hmma<96, 256>,
                         cudaFuncAttributeMaxDynamicSharedMemorySize, SMEM_QKV);
    cudaFuncSetAttribute(gemm_hmma<128, 64>,
                         cudaFuncAttributeMaxDynamicSharedMemorySize, SMEM_PROJ);

    // 1) QKV: C(192,3136) = qkv_w(192,256) @ x(256,3136), per batch
    gemm_hmma<96, 256><<<dim3(25, 2, 16), 256, SMEM_QKV>>>(x, qkv_w, qkv_b, qkv_p);

    // 2) Fused sliding attention
    attn2<<<dim3(WID / AT_ROWS, NHD, 16), 224>>>(
        qkv_p, dc_b, dc1_w, dc1_b, rpb, hid_p);

    // 3) Proj: out(256,3136) = proj_w(256,64) @ hid(64,3136), per batch
    gemm_hmma<128, 64><<<dim3(25, 2, 16), 256, SMEM_PROJ>>>(hid_p, proj_w, proj_b, out);
}